// round 8
// baseline (speedup 1.0000x reference)
#include <cuda_runtime.h>
#include <math.h>

// Lin2d: x <- x @ Mt, 1000 times, Mt = [[c,-s],[s,c]] (float32 c,s).
// Collapsed to one complex multiply by w = (c - i*s)^1000 (host double math).
// Streaming kernel: 2 independent float4s per thread (MLP=2), evict-first
// cache hints (__ldcs/__stcs) since each byte is touched exactly once.

__global__ void lin2d_apply_kernel(const float4* __restrict__ in,
                                   float4* __restrict__ out,
                                   int n4, float wr, float wi) {
    int base = blockIdx.x * (blockDim.x * 2) + threadIdx.x;
    int i1 = base + blockDim.x;

    if (i1 < n4) {
        // Fast path: both elements in range (all blocks when n4 % (2*bdim) == 0).
        float4 v0 = __ldcs(in + base);
        float4 v1 = __ldcs(in + i1);
        float4 r0, r1;
        r0.x = fmaf(wr, v0.x, -wi * v0.y);
        r0.y = fmaf(wi, v0.x,  wr * v0.y);
        r0.z = fmaf(wr, v0.z, -wi * v0.w);
        r0.w = fmaf(wi, v0.z,  wr * v0.w);
        r1.x = fmaf(wr, v1.x, -wi * v1.y);
        r1.y = fmaf(wi, v1.x,  wr * v1.y);
        r1.z = fmaf(wr, v1.z, -wi * v1.w);
        r1.w = fmaf(wi, v1.z,  wr * v1.w);
        __stcs(out + base, r0);
        __stcs(out + i1, r1);
    } else if (base < n4) {
        float4 v0 = __ldcs(in + base);
        float4 r0;
        r0.x = fmaf(wr, v0.x, -wi * v0.y);
        r0.y = fmaf(wi, v0.x,  wr * v0.y);
        r0.z = fmaf(wr, v0.z, -wi * v0.w);
        r0.w = fmaf(wi, v0.z,  wr * v0.w);
        __stcs(out + base, r0);
    }
}

extern "C" void kernel_launch(void* const* d_in, const int* in_sizes, int n_in,
                              void* d_out, int out_size) {
    const float* x = (const float*)d_in[0];
    float* y = (float*)d_out;
    const int n = in_sizes[0];       // total floats = BATCH*2 (multiple of 4)
    const int n4 = n / 4;

    // Host-side constants (pure math at capture time; deterministic).
    const double theta = 3.14159265358979323846 / 100.0;
    const double c = (double)((float)cos(theta));
    const double s = (double)((float)sin(theta));
    const int N = 1000;
    const double r   = hypot(c, s);
    const double phi = atan2(s, c);
    const double mag = pow(r, (double)N);
    // w = (c - i*s)^N = mag * (cos(N*phi) - i*sin(N*phi))
    const float wr = (float)(mag * cos((double)N * phi));
    const float wi = (float)(-mag * sin((double)N * phi));

    const int threads = 256;
    const int per_block = threads * 2;
    const int blocks = (n4 + per_block - 1) / per_block;
    lin2d_apply_kernel<<<blocks, threads>>>((const float4*)x, (float4*)y,
                                            n4, wr, wi);
}